// round 16
// baseline (speedup 1.0000x reference)
#include <cuda_runtime.h>
#include <cuda_fp16.h>
#include <cstdint>
#include <cstddef>

#define N      16384
#define C      128
#define KNN    9
#define KCAND  20
#define COUT   256
#define BUFCAP 1024
#define NTILE  (N / 128)       // 128 column tiles
#define SPITCH 36              // smem row pitch in 32-bit words (32 data + 4 pad)
#define CHWORDS (128 * SPITCH) // words per 128x(64 bf16) chunk buffer
#define TPITCH 132             // transpose buffer pitch (words)
#define RROWS  4               // rows per refine block

// Scratch (static __device__ arrays per harness rules; no cudaMalloc anywhere)
__device__ float    g_sq[N];
__device__ uint32_t g_xb[(size_t)N * (C / 2)];  // x as packed bf16x2 (4 MB)
__device__ __half   g_dist[(size_t)N * N];      // 512 MB half distance matrix
__device__ float    g_rowmin[N * NTILE];        // per (row, col tile) min of stored halves
__device__ int      g_cand[N * KCAND];
__device__ int      g_nbr[N * KNN];
__device__ float    g_x2[(size_t)N * C];

// monotone float->unsigned key (order-preserving)
__device__ __forceinline__ unsigned fkey(float f) {
    unsigned u = __float_as_uint(f);
    return (u & 0x80000000u) ? ~u : (u | 0x80000000u);
}
__device__ __forceinline__ float funkey(unsigned k) {
    return __uint_as_float((k & 0x80000000u) ? (k & 0x7fffffffu) : ~k);
}

// ---------------------------------------------------------------------------
// 1) fused: squared norms (LLVM/XLA vectorized-reduce order) + bf16x2 pack.
// ---------------------------------------------------------------------------
__global__ void prep_kernel(const float* __restrict__ x) {
    int i = blockIdx.x * blockDim.x + threadIdx.x;
    if (i >= N) return;
    const float* r = x + (size_t)i * C;
    uint32_t* pb = g_xb + (size_t)i * (C / 2);
    float p[8];
#pragma unroll
    for (int l = 0; l < 8; l++) p[l] = 0.f;
#pragma unroll
    for (int k = 0; k < C / 8; k++) {
        float v[8];
#pragma unroll
        for (int l = 0; l < 8; l++) {
            v[l] = r[8 * k + l];
            p[l] = fmaf(v[l], v[l], p[l]);
        }
#pragma unroll
        for (int q = 0; q < 4; q++) {
            uint32_t pk;
            asm("cvt.rn.bf16x2.f32 %0, %1, %2;" : "=r"(pk)
                : "f"(v[2 * q + 1]), "f"(v[2 * q]));
            pb[4 * k + q] = pk;
        }
    }
    float v0 = p[0] + p[4];
    float v1 = p[1] + p[5];
    float v2 = p[2] + p[6];
    float v3 = p[3] + p[7];
    g_sq[i] = (v0 + v2) + (v1 + v3);
}

// ---------------------------------------------------------------------------
// 2) SYMMETRIC monolithic distance GEMM, bf16 mma.sync m16n8k16, cp.async
//    double-buffered (2 chunks of K=64). Nomination only -- fp32-exact refine
//    is the ranking authority. dist stored fp16; all minima over stored halves.
// ---------------------------------------------------------------------------
__device__ __forceinline__ void stage_chunk(int bi, int bj, int kc,
                                            uint32_t* As, uint32_t* Bs, int tid) {
#pragma unroll
    for (int v = 0; v < 4; v++) {
        int idx = tid + v * 256;         // 0..1023
        int row = idx >> 3;              // 0..127
        int c4  = (idx & 7) << 2;        // 0..28  (words)
        const uint32_t* ga = &g_xb[(size_t)(bi + row) * (C / 2) + kc * 32 + c4];
        unsigned da = (unsigned)__cvta_generic_to_shared(&As[row * SPITCH + c4]);
        asm volatile("cp.async.cg.shared.global [%0], [%1], 16;" :: "r"(da), "l"(ga));
        const uint32_t* gb = &g_xb[(size_t)(bj + row) * (C / 2) + kc * 32 + c4];
        unsigned db = (unsigned)__cvta_generic_to_shared(&Bs[row * SPITCH + c4]);
        asm volatile("cp.async.cg.shared.global [%0], [%1], 16;" :: "r"(db), "l"(gb));
    }
}

__global__ __launch_bounds__(256, 2)
void dist_kernel() {
    if (blockIdx.y > blockIdx.x) return;   // lower-triangle tiles mirrored

    extern __shared__ uint32_t smu[];
    uint32_t* Abuf[2] = { smu,            smu + 2 * CHWORDS };
    uint32_t* Bbuf[2] = { smu + CHWORDS,  smu + 3 * CHWORDS };
    unsigned* rmin = smu + 4 * CHWORDS;
    unsigned* cmin = rmin + 128;
    float*    smf  = (float*)smu;          // transpose buffer (reuse staging)

    const int tid  = threadIdx.x;
    const int warp = tid >> 5;
    const int lane = tid & 31;
    const int g    = lane >> 2;     // groupID
    const int tig  = lane & 3;      // thread-in-group
    const int wm   = warp & 3;      // warp row  (32 rows)
    const int wn   = warp >> 2;     // warp col  (64 cols)
    const int bi   = blockIdx.y * 128;
    const int bj   = blockIdx.x * 128;
    const bool mirror = (bi != bj);

    if (tid < 128) { rmin[tid] = 0xFFFFFFFFu; cmin[tid] = 0xFFFFFFFFu; }

    float acc[2][8][4];
#pragma unroll
    for (int mt = 0; mt < 2; mt++)
#pragma unroll
        for (int nt = 0; nt < 8; nt++)
#pragma unroll
            for (int e = 0; e < 4; e++) acc[mt][nt][e] = 0.f;

    stage_chunk(bi, bj, 0, Abuf[0], Bbuf[0], tid);
    asm volatile("cp.async.commit_group;");

#pragma unroll
    for (int kc = 0; kc < 2; kc++) {
        if (kc < 1) {
            stage_chunk(bi, bj, 1, Abuf[1], Bbuf[1], tid);
            asm volatile("cp.async.commit_group;");
            asm volatile("cp.async.wait_group 1;");
        } else {
            asm volatile("cp.async.wait_group 0;");
        }
        __syncthreads();

        const uint32_t* As = Abuf[kc];
        const uint32_t* Bs = Bbuf[kc];
#pragma unroll
        for (int ks = 0; ks < 4; ks++) {
            const int k0 = ks * 8;       // 8 words = 16 bf16 elements
            uint32_t a[2][4];
#pragma unroll
            for (int mt = 0; mt < 2; mt++) {
                int rbase = (wm * 32 + mt * 16 + g) * SPITCH + k0 + tig;
                a[mt][0] = As[rbase];
                a[mt][1] = As[rbase + 8 * SPITCH];
                a[mt][2] = As[rbase + 4];
                a[mt][3] = As[rbase + 8 * SPITCH + 4];
            }
            uint32_t b[8][2];
#pragma unroll
            for (int nt = 0; nt < 8; nt++) {
                int cbase = (wn * 64 + nt * 8 + g) * SPITCH + k0 + tig;
                b[nt][0] = Bs[cbase];
                b[nt][1] = Bs[cbase + 4];
            }
#pragma unroll
            for (int mt = 0; mt < 2; mt++)
#pragma unroll
                for (int nt = 0; nt < 8; nt++)
                    asm volatile(
                        "mma.sync.aligned.m16n8k16.row.col.f32.bf16.bf16.f32 "
                        "{%0,%1,%2,%3}, {%4,%5,%6,%7}, {%8,%9}, {%0,%1,%2,%3};"
                        : "+f"(acc[mt][nt][0]), "+f"(acc[mt][nt][1]),
                          "+f"(acc[mt][nt][2]), "+f"(acc[mt][nt][3])
                        : "r"(a[mt][0]), "r"(a[mt][1]), "r"(a[mt][2]), "r"(a[mt][3]),
                          "r"(b[nt][0]), "r"(b[nt][1]));
        }
        __syncthreads();
    }
    // staging smem is free from here on (reused as transpose buffer)

    const float INFV = __int_as_float(0x7f800000);
    float cm[8][2];
#pragma unroll
    for (int nt = 0; nt < 8; nt++) { cm[nt][0] = INFV; cm[nt][1] = INFV; }

#pragma unroll
    for (int mt = 0; mt < 2; mt++) {
        int rl = wm * 32 + mt * 16 + g;        // local row (lo); hi = +8
        int r_lo = bi + rl, r_hi = r_lo + 8;
        float si_lo = g_sq[r_lo], si_hi = g_sq[r_hi];
        float mn_lo = INFV, mn_hi = INFV;
#pragma unroll
        for (int nt = 0; nt < 8; nt++) {
            int cl = wn * 64 + nt * 8 + 2 * tig;   // local col
            int c0 = bj + cl;
            float sj0 = g_sq[c0], sj1 = g_sq[c0 + 1];
            float d00 = (si_lo + sj0) - 2.f * acc[mt][nt][0];
            float d01 = (si_lo + sj1) - 2.f * acc[mt][nt][1];
            float d10 = (si_hi + sj0) - 2.f * acc[mt][nt][2];
            float d11 = (si_hi + sj1) - 2.f * acc[mt][nt][3];
            if (r_lo == c0)     d00 = INFV;
            if (r_lo == c0 + 1) d01 = INFV;
            if (r_hi == c0)     d10 = INFV;
            if (r_hi == c0 + 1) d11 = INFV;
            __half h00 = __float2half_rn(d00), h01 = __float2half_rn(d01);
            __half h10 = __float2half_rn(d10), h11 = __float2half_rn(d11);
            float f00 = __half2float(h00), f01 = __half2float(h01);
            float f10 = __half2float(h10), f11 = __half2float(h11);
            mn_lo = fminf(mn_lo, fminf(f00, f01));
            mn_hi = fminf(mn_hi, fminf(f10, f11));
            *reinterpret_cast<__half2*>(&g_dist[(size_t)r_lo * N + c0]) =
                __halves2half2(h00, h01);
            *reinterpret_cast<__half2*>(&g_dist[(size_t)r_hi * N + c0]) =
                __halves2half2(h10, h11);
            if (mirror) {
                cm[nt][0] = fminf(cm[nt][0], fminf(f00, f10));
                cm[nt][1] = fminf(cm[nt][1], fminf(f01, f11));
                smf[cl * TPITCH + rl]           = f00;
                smf[(cl + 1) * TPITCH + rl]     = f01;
                smf[cl * TPITCH + rl + 8]       = f10;
                smf[(cl + 1) * TPITCH + rl + 8] = f11;
            }
        }
        mn_lo = fminf(mn_lo, __shfl_xor_sync(0xffffffffu, mn_lo, 1));
        mn_lo = fminf(mn_lo, __shfl_xor_sync(0xffffffffu, mn_lo, 2));
        mn_hi = fminf(mn_hi, __shfl_xor_sync(0xffffffffu, mn_hi, 1));
        mn_hi = fminf(mn_hi, __shfl_xor_sync(0xffffffffu, mn_hi, 2));
        if (tig == 0) {
            atomicMin(&rmin[wm * 32 + mt * 16 + g],     fkey(mn_lo));
            atomicMin(&rmin[wm * 32 + mt * 16 + g + 8], fkey(mn_hi));
        }
    }

    if (mirror) {
#pragma unroll
        for (int nt = 0; nt < 8; nt++)
#pragma unroll
            for (int e = 0; e < 2; e++) {
                float v = cm[nt][e];
                v = fminf(v, __shfl_xor_sync(0xffffffffu, v, 4));
                v = fminf(v, __shfl_xor_sync(0xffffffffu, v, 8));
                v = fminf(v, __shfl_xor_sync(0xffffffffu, v, 16));
                if (lane < 4)
                    atomicMin(&cmin[wn * 64 + nt * 8 + 2 * tig + e], fkey(v));
            }
    }
    __syncthreads();

    if (tid < 128)
        g_rowmin[(bi + tid) * NTILE + blockIdx.x] = funkey(rmin[tid]);

    if (mirror) {
        // coalesced mirrored-tile store (half round-trip is bit-exact)
#pragma unroll
        for (int it = 0; it < 16; it++) {
            int idx = tid + it * 256;     // 0..4095
            int tr  = idx >> 5;           // 0..127
            int c4  = (idx & 31) << 2;    // 0..124
            float4 v = *reinterpret_cast<const float4*>(&smf[tr * TPITCH + c4]);
            __half2 h0 = __halves2half2(__float2half_rn(v.x), __float2half_rn(v.y));
            __half2 h1 = __halves2half2(__float2half_rn(v.z), __float2half_rn(v.w));
            *reinterpret_cast<__half2*>(&g_dist[(size_t)(bj + tr) * N + bi + c4])     = h0;
            *reinterpret_cast<__half2*>(&g_dist[(size_t)(bj + tr) * N + bi + c4 + 2]) = h1;
        }
        if (tid < 128)
            g_rowmin[(bj + tid) * NTILE + blockIdx.y] = funkey(cmin[tid]);
    }
}

// ---------------------------------------------------------------------------
// 3) per-row top-20 via hierarchical tile-min selection.
//    tau = tile-min with rank KCAND-1 among the 128 tile minima (tight).
//    Scan only tiles with min <= tau, compact, rank-select by (val, idx).
// ---------------------------------------------------------------------------
__global__ __launch_bounds__(128)
void topk_kernel() {
    __shared__ float tmin[NTILE];
    __shared__ float s_tau;
    __shared__ int   s_act[NTILE];
    __shared__ int   s_nact;
    __shared__ int   s_cnt;
    __shared__ float bval[BUFCAP];
    __shared__ int   bidx[BUFCAP];

    const int row  = blockIdx.x;
    const __half* d = g_dist + (size_t)row * N;
    const int tid  = threadIdx.x;

    tmin[tid] = g_rowmin[row * NTILE + tid];
    if (tid == 0) { s_cnt = 0; s_nact = 0; }
    __syncthreads();

    // tau = tile-min with rank KCAND-1 under (val, tile) order
    float mv = tmin[tid];
    int rank = 0;
#pragma unroll 8
    for (int t = 0; t < NTILE; t++) {
        float ov = tmin[t];
        rank += (ov < mv) || (ov == mv && t < tid);
    }
    if (rank == KCAND - 1) s_tau = mv;
    __syncthreads();
    const float tau = s_tau;

    // active tiles (min <= tau)
    if (tmin[tid] <= tau) {
        int p = atomicAdd(&s_nact, 1);
        s_act[p] = tid;
    }
    __syncthreads();
    const int nact = s_nact;

    // scan active tiles, compact elements <= tau
    for (int a = 0; a < nact; a++) {
        int t = s_act[a];
        float v = __half2float(d[t * 128 + tid]);
        if (v <= tau) {
            int p = atomicAdd(&s_cnt, 1);
            if (p < BUFCAP) { bval[p] = v; bidx[p] = t * 128 + tid; }
        }
    }
    __syncthreads();
    const int m = (s_cnt < BUFCAP) ? s_cnt : BUFCAP;

    // rank-select: entry e's rank = #{f : (v_f, i_f) < (v_e, i_e)}
    for (int e = tid; e < m; e += 128) {
        float v = bval[e];
        int   j = bidx[e];
        int r = 0;
        for (int t = 0; t < m; t++) {
            float ov = bval[t];
            r += (ov < v) || (ov == v && bidx[t] < j);
        }
        if (r < KCAND) g_cand[row * KCAND + r] = j;
    }
}

// ---------------------------------------------------------------------------
// 3b) authoritative fp32 re-rank of the 20 candidates (reference arithmetic:
//     single ascending-k fmaf chain, d=(sq_i+sq_j)-2*dot, tie->lower index).
//     All candidate rows staged through smem with coalesced loads; the
//     bit-exact serial chains then run out of LDS.
// ---------------------------------------------------------------------------
__global__ __launch_bounds__(128)
void refine_kernel(const float* __restrict__ x) {
    __shared__ float sxi[RROWS][132];
    __shared__ float sc[RROWS * KCAND][132];   // 80 rows x 132 words = 42 KB
    __shared__ int   scid[RROWS * KCAND];

    const int tid  = threadIdx.x;
    const int warp = tid >> 5;
    const int lane = tid & 31;
    const int row0 = blockIdx.x * RROWS;

    if (tid < RROWS * KCAND)
        scid[tid] = g_cand[(row0 + tid / KCAND) * KCAND + tid % KCAND];

    // stage query rows (coalesced)
    for (int idx = tid; idx < RROWS * 32; idx += 128) {
        int r = idx >> 5, w = idx & 31;
        *reinterpret_cast<float4*>(&sxi[r][w * 4]) =
            *reinterpret_cast<const float4*>(&x[(size_t)(row0 + r) * C + w * 4]);
    }
    __syncthreads();   // scid ready

    // stage candidate rows: 32 consecutive lanes cover one 512B row
    for (int idx = tid; idx < RROWS * KCAND * 32; idx += 128) {
        int cr = idx >> 5, w = idx & 31;
        int j = scid[cr];
        *reinterpret_cast<float4*>(&sc[cr][w * 4]) =
            *reinterpret_cast<const float4*>(&x[(size_t)j * C + w * 4]);
    }
    __syncthreads();

    const int row = row0 + warp;
    float d = __int_as_float(0x7f800000);
    int   j = 0x7fffffff;
    if (lane < KCAND) {
        int cr = warp * KCAND + lane;
        j = scid[cr];
        float acc = 0.f;
#pragma unroll
        for (int k = 0; k < C; k += 4) {
            float4 v = *reinterpret_cast<const float4*>(&sc[cr][k]);
            acc = fmaf(sxi[warp][k + 0], v.x, acc);
            acc = fmaf(sxi[warp][k + 1], v.y, acc);
            acc = fmaf(sxi[warp][k + 2], v.z, acc);
            acc = fmaf(sxi[warp][k + 3], v.w, acc);
        }
        d = (g_sq[row] + g_sq[j]) - 2.f * acc;
    }

    float dv[KCAND];
    int   di[KCAND];
#pragma unroll
    for (int t = 0; t < KCAND; t++) {
        dv[t] = __shfl_sync(0xffffffffu, d, t);
        di[t] = __shfl_sync(0xffffffffu, j, t);
    }
    if (lane == 0) {
#pragma unroll
        for (int a = 0; a < KCAND - 1; a++)
#pragma unroll
            for (int bq = 0; bq < KCAND - 1; bq++) {
                bool sw = dv[bq] > dv[bq + 1] ||
                          (dv[bq] == dv[bq + 1] && di[bq] > di[bq + 1]);
                float tv = sw ? dv[bq + 1] : dv[bq];
                dv[bq + 1] = sw ? dv[bq] : dv[bq + 1]; dv[bq] = tv;
                int ti = sw ? di[bq + 1] : di[bq];
                di[bq + 1] = sw ? di[bq] : di[bq + 1]; di[bq] = ti;
            }
#pragma unroll
        for (int t = 0; t < KNN; t++) g_nbr[row * KNN + t] = di[t];
    }
}

// ---------------------------------------------------------------------------
// 4) x2 = x + rel_pos_table[rel]
// ---------------------------------------------------------------------------
__global__ void relpos_kernel(const float* __restrict__ x, const float* __restrict__ tab) {
    int idx = blockIdx.x * blockDim.x + threadIdx.x;
    int i   = idx >> 7;
    int c   = idx & 127;
    int rel = (i >> 7) - (i & 127) + (C - 1);
    g_x2[idx] = x[idx] + tab[(size_t)rel * C + c];
}

// ---------------------------------------------------------------------------
// 5) gather + max-relative + concat-GEMM (+ bias at the end). 16 rows/block.
// ---------------------------------------------------------------------------
__global__ __launch_bounds__(256)
void final_kernel(const float* __restrict__ W, const float* __restrict__ b,
                  float* __restrict__ out) {
    __shared__ float feat[16][260];
    const int r0   = blockIdx.x * 16;
    const int tid  = threadIdx.x;
    const int half = tid >> 7;
    const int c    = tid & 127;
    const float NEGINF = __int_as_float(0xff800000);

#pragma unroll
    for (int rr = 0; rr < 16; rr += 2) {
        int r = rr + half;
        int i = r0 + r;
        float xi = g_x2[(size_t)i * C + c];
        float m  = NEGINF;
#pragma unroll
        for (int k = 0; k < KNN; k++) {
            int j = g_nbr[i * KNN + k];
            m = fmaxf(m, g_x2[(size_t)j * C + c] - xi);
        }
        feat[r][c]     = xi;
        feat[r][C + c] = m;
    }
    __syncthreads();

    const int o = tid;
    float acc[16];
#pragma unroll
    for (int r = 0; r < 16; r++) acc[r] = 0.f;

    for (int f = 0; f < 2 * C; f += 4) {
        float w0 = W[(size_t)(f + 0) * COUT + o];
        float w1 = W[(size_t)(f + 1) * COUT + o];
        float w2 = W[(size_t)(f + 2) * COUT + o];
        float w3 = W[(size_t)(f + 3) * COUT + o];
#pragma unroll
        for (int r = 0; r < 16; r++) {
            float4 fv = *reinterpret_cast<const float4*>(&feat[r][f]);
            acc[r] = fmaf(fv.x, w0, acc[r]);
            acc[r] = fmaf(fv.y, w1, acc[r]);
            acc[r] = fmaf(fv.z, w2, acc[r]);
            acc[r] = fmaf(fv.w, w3, acc[r]);
        }
    }
    float bias = b[o];
#pragma unroll
    for (int r = 0; r < 16; r++)
        out[(size_t)(r0 + r) * COUT + o] = acc[r] + bias;
}

// ---------------------------------------------------------------------------
extern "C" void kernel_launch(void* const* d_in, const int* in_sizes, int n_in,
                              void* d_out, int out_size) {
    const float* x   = (const float*)d_in[0];
    const float* tab = (const float*)d_in[1];
    const float* W   = (const float*)d_in[2];
    const float* b   = (const float*)d_in[3];
    float* out = (float*)d_out;
    (void)in_sizes; (void)n_in; (void)out_size;

    const int smem_bytes = (4 * CHWORDS) * (int)sizeof(uint32_t) + 256 * (int)sizeof(unsigned);
    static bool attr_set = false;
    if (!attr_set) {
        cudaFuncSetAttribute(dist_kernel,
                             cudaFuncAttributeMaxDynamicSharedMemorySize, smem_bytes);
        attr_set = true;
    }

    prep_kernel<<<(N + 255) / 256, 256>>>(x);
    dist_kernel<<<dim3(NTILE, NTILE), 256, smem_bytes>>>();
    topk_kernel<<<N, 128>>>();
    refine_kernel<<<N / RROWS, 128>>>(x);
    relpos_kernel<<<(N * C) / 256, 256>>>(x, tab);
    final_kernel<<<N / 16, 256>>>(W, b, out);
}